// round 7
// baseline (speedup 1.0000x reference)
#include <cuda_runtime.h>
#include <cuda_bf16.h>
#include <math.h>

// Loss = 1.0*n2v + 0.2*wav + 0.01*tv over pred/noisy (64,1,512,512) f32, mask bool.
// Identity: |c - soft_threshold(c, thr)| == min(|c|, thr).
// Row-pair register scheme: lane l, warp w, item k owns rows (2p, 2p+1), p=4w+k,
// cols 4l..4l+3. DWT L1 + within-pair TV from registers; only even rows hit smem.
// p4/n4 are pre-offset by img_off: index with IMAGE-LOCAL offsets only.

#define B_   64
#define H_   512
#define W_   512
#define TH   64
#define TW   128
#define NBLK ((W_/TW)*(H_/TH)*B_)      // 2048

#define THR1 (50.0f / 255.0f)
#define THR2 (25.0f / 255.0f)
#define THR3 (12.5f / 255.0f)

// per-block partials: [0]=n2v [1]=mask [2]=wav64 [3]=wav128 [4]=wav256 [5]=tv
__device__ float    g_part[6][NBLK];
__device__ unsigned g_done;            // zero-init; last block resets each replay

__device__ __forceinline__ float clipf(float x) {
    return fminf(fmaxf(x, 0.0f), 1.0f);
}

__global__ __launch_bounds__(256, 7)
void loss_kernel(const float* __restrict__ pred,
                 const float* __restrict__ noisy,
                 const unsigned char* __restrict__ mask8,
                 const unsigned int* __restrict__ mask32,
                 float* __restrict__ out) {
    __shared__ float4 tops[33 * 33];   // 32 pair-top rows + halo row 64; 32 f4/row + 1 pad
    __shared__ float  ll1[32 * 68];    // level-1 LL (32x64), padded stride
    __shared__ float  ll2[16 * 36];
    __shared__ float  red[6][8];
    __shared__ bool   amLast;

    const int tid  = threadIdx.x;
    const int wid  = tid >> 5;
    const int lane = tid & 31;
    const int b    = blockIdx.z;
    const int r0   = blockIdx.y * TH;
    const int c0   = blockIdx.x * TW;
    const int bid  = (blockIdx.z * gridDim.y + blockIdx.y) * gridDim.x + blockIdx.x;
    const size_t img_off = (size_t)b * H_ * W_;
    const float4* p4 = (const float4*)(pred  + img_off);
    const float4* n4 = (const float4*)(noisy + img_off);
    const bool last_row_tile = (r0 + TH == H_);
    const bool last_col_tile = (c0 + TW == W_);

    // ---- mask layout probe: first 512 words (2KB, L2-resident across blocks).
    unsigned pw0 = mask32[tid], pw1 = mask32[tid + 256];
    int bad = ((pw0 != 0u && pw0 != 1u && pw0 != 0x3F800000u) ||
               (pw1 != 0u && pw1 != 1u && pw1 != 0x3F800000u)) ? 1 : 0;
    const int mask_is_byte = __syncthreads_or(bad);

    float a_n2v = 0.f, a_msk = 0.f, a_tv = 0.f;
    float a_w1 = 0.f, a_w2 = 0.f, a_w3 = 0.f;
    float4 bt[4];                      // bottom rows retained across the sync

    // ===== PHASE A: load pair, n2v+mask, within-pair TV, DWT L1, stash tops =====
    #pragma unroll
    for (int k = 0; k < 4; k++) {
        int pr = wid * 4 + k;              // pair index 0..31
        int gr = r0 + 2 * pr;
        const float4* rowt = p4 + (size_t)gr * (W_ / 4) + (c0 >> 2);
        float4 t = __ldg(rowt + lane);
        float4 bo = __ldg(rowt + (W_ / 4) + lane);
        t.x = clipf(t.x); t.y = clipf(t.y); t.z = clipf(t.z); t.w = clipf(t.w);
        bo.x = clipf(bo.x); bo.y = clipf(bo.y); bo.z = clipf(bo.z); bo.w = clipf(bo.w);

        size_t lofft = (size_t)gr * W_ + c0 + 4 * lane;
        size_t pixt  = img_off + lofft;
        float tm0, tm1, tm2, tm3, bm0, bm1, bm2, bm3;
        bool any_t, any_b;
        if (mask_is_byte) {
            unsigned wt = __ldg((const unsigned*)(mask8 + pixt));
            unsigned wb = __ldg((const unsigned*)(mask8 + pixt + W_));
            any_t = wt != 0u; any_b = wb != 0u;
            tm0 = (wt & 0x000000FFu) ? 1.f : 0.f; tm1 = (wt & 0x0000FF00u) ? 1.f : 0.f;
            tm2 = (wt & 0x00FF0000u) ? 1.f : 0.f; tm3 = (wt & 0xFF000000u) ? 1.f : 0.f;
            bm0 = (wb & 0x000000FFu) ? 1.f : 0.f; bm1 = (wb & 0x0000FF00u) ? 1.f : 0.f;
            bm2 = (wb & 0x00FF0000u) ? 1.f : 0.f; bm3 = (wb & 0xFF000000u) ? 1.f : 0.f;
        } else {
            uint4 wt = __ldg((const uint4*)(mask32 + pixt));
            uint4 wb = __ldg((const uint4*)(mask32 + pixt + W_));
            any_t = (wt.x | wt.y | wt.z | wt.w) != 0u;
            any_b = (wb.x | wb.y | wb.z | wb.w) != 0u;
            tm0 = wt.x ? 1.f : 0.f; tm1 = wt.y ? 1.f : 0.f;
            tm2 = wt.z ? 1.f : 0.f; tm3 = wt.w ? 1.f : 0.f;
            bm0 = wb.x ? 1.f : 0.f; bm1 = wb.y ? 1.f : 0.f;
            bm2 = wb.z ? 1.f : 0.f; bm3 = wb.w ? 1.f : 0.f;
        }
        a_msk += (tm0 + tm1) + (tm2 + tm3) + (bm0 + bm1) + (bm2 + bm3);
        if (any_t) {
            float4 nv = __ldg(&n4[lofft >> 2]);
            a_n2v += fabsf(t.x - nv.x) * tm0 + fabsf(t.y - nv.y) * tm1
                   + fabsf(t.z - nv.z) * tm2 + fabsf(t.w - nv.w) * tm3;
        }
        if (any_b) {
            float4 nv = __ldg(&n4[(lofft + W_) >> 2]);
            a_n2v += fabsf(bo.x - nv.x) * bm0 + fabsf(bo.y - nv.y) * bm1
                   + fabsf(bo.z - nv.z) * bm2 + fabsf(bo.w - nv.w) * bm3;
        }

        // right halo (col c0+128) for lane 31
        float tr = 0.f, br = 0.f;
        if (lane == 31 && !last_col_tile) {
            const float* ph = pred + img_off + (size_t)gr * W_ + c0 + TW;
            tr = clipf(__ldg(ph));
            br = clipf(__ldg(ph + W_));
        }
        float sht = __shfl_down_sync(0xFFFFFFFFu, t.x, 1);
        float shb = __shfl_down_sync(0xFFFFFFFFu, bo.x, 1);
        float nt = (lane == 31) ? tr : sht;
        float nb = (lane == 31) ? br : shb;
        float hm = (lane == 31 && last_col_tile) ? 0.f : 1.f;

        a_tv += fabsf(t.y - t.x) + fabsf(t.z - t.y) + fabsf(t.w - t.z) + hm * fabsf(nt - t.w)
              + fabsf(bo.y - bo.x) + fabsf(bo.z - bo.y) + fabsf(bo.w - bo.z) + hm * fabsf(nb - bo.w)
              + fabsf(bo.x - t.x) + fabsf(bo.y - t.y) + fabsf(bo.z - t.z) + fabsf(bo.w - t.w);

        // DWT level 1 from registers (finest => THR3)
        float s0 = t.x + t.y, t0 = bo.x + bo.y, u0 = t.x - t.y, v0 = bo.x - bo.y;
        float ch0 = (s0 - t0) * 0.5f, cv0 = (u0 + v0) * 0.5f, cd0 = (u0 - v0) * 0.5f;
        float s1 = t.z + t.w, t1 = bo.z + bo.w, u1 = t.z - t.w, v1 = bo.z - bo.w;
        float ch1 = (s1 - t1) * 0.5f, cv1 = (u1 + v1) * 0.5f, cd1 = (u1 - v1) * 0.5f;
        a_w3 += fminf(fabsf(ch0), THR3) + fminf(fabsf(cv0), THR3) + fminf(fabsf(cd0), THR3)
              + fminf(fabsf(ch1), THR3) + fminf(fabsf(cv1), THR3) + fminf(fabsf(cd1), THR3);
        ((float2*)&ll1[pr * 68])[lane] = make_float2((s0 + t0) * 0.5f, (s1 + t1) * 0.5f);

        tops[pr * 33 + lane] = t;
        bt[k] = bo;
    }
    // halo row 64 -> tops[32]
    if (wid == 0) {
        float4 x = make_float4(0.f, 0.f, 0.f, 0.f);
        if (!last_row_tile) {
            x = __ldg(&p4[(size_t)(r0 + TH) * (W_ / 4) + (c0 >> 2) + lane]);
            x.x = clipf(x.x); x.y = clipf(x.y); x.z = clipf(x.z); x.w = clipf(x.w);
        }
        tops[32 * 33 + lane] = x;
    }
    __syncthreads();

    // ===== between-pair vertical TV (reads next pair's top row) =====
    #pragma unroll
    for (int k = 0; k < 4; k++) {
        int pr = wid * 4 + k;
        float4 nt = tops[(pr + 1) * 33 + lane];
        float4 bo = bt[k];
        float vm = (pr == 31 && last_row_tile) ? 0.f : 1.f;
        a_tv += vm * (fabsf(nt.x - bo.x) + fabsf(nt.y - bo.y)
                    + fabsf(nt.z - bo.z) + fabsf(nt.w - bo.w));
    }

    // ===== Haar level 2: 32x64 -> 16x32 (THR2) =====
    {
        int i = tid >> 4, j = tid & 15;
        float4 tp = ((const float4*)&ll1[(2 * i) * 68])[j];
        float4 bo = ((const float4*)&ll1[(2 * i + 1) * 68])[j];
        float s0 = tp.x + tp.y, t0 = bo.x + bo.y, u0 = tp.x - tp.y, v0 = bo.x - bo.y;
        float ch0 = (s0 - t0) * 0.5f, cv0 = (u0 + v0) * 0.5f, cd0 = (u0 - v0) * 0.5f;
        float s1 = tp.z + tp.w, t1 = bo.z + bo.w, u1 = tp.z - tp.w, v1 = bo.z - bo.w;
        float ch1 = (s1 - t1) * 0.5f, cv1 = (u1 + v1) * 0.5f, cd1 = (u1 - v1) * 0.5f;
        a_w2 += fminf(fabsf(ch0), THR2) + fminf(fabsf(cv0), THR2) + fminf(fabsf(cd0), THR2)
              + fminf(fabsf(ch1), THR2) + fminf(fabsf(cv1), THR2) + fminf(fabsf(cd1), THR2);
        ll2[i * 36 + 2 * j]     = (s0 + t0) * 0.5f;
        ll2[i * 36 + 2 * j + 1] = (s1 + t1) * 0.5f;
    }
    __syncthreads();

    // ===== Haar level 3: 16x32 -> 8x16 details (THR1) =====
    if (tid < 64) {
        int i = tid >> 3, j = tid & 7;
        float4 tp = ((const float4*)&ll2[(2 * i) * 36])[j];
        float4 bo = ((const float4*)&ll2[(2 * i + 1) * 36])[j];
        float s0 = tp.x + tp.y, t0 = bo.x + bo.y, u0 = tp.x - tp.y, v0 = bo.x - bo.y;
        float ch0 = (s0 - t0) * 0.5f, cv0 = (u0 + v0) * 0.5f, cd0 = (u0 - v0) * 0.5f;
        float s1 = tp.z + tp.w, t1 = bo.z + bo.w, u1 = tp.z - tp.w, v1 = bo.z - bo.w;
        float ch1 = (s1 - t1) * 0.5f, cv1 = (u1 + v1) * 0.5f, cd1 = (u1 - v1) * 0.5f;
        a_w1 += fminf(fabsf(ch0), THR1) + fminf(fabsf(cv0), THR1) + fminf(fabsf(cd0), THR1)
              + fminf(fabsf(ch1), THR1) + fminf(fabsf(cv1), THR1) + fminf(fabsf(cd1), THR1);
    }

    // ===== block reduce, write partials =====
    float vals[6] = {a_n2v, a_msk, a_w1, a_w2, a_w3, a_tv};
    #pragma unroll
    for (int k = 0; k < 6; k++) {
        float s = vals[k];
        #pragma unroll
        for (int o = 16; o > 0; o >>= 1) s += __shfl_down_sync(0xFFFFFFFFu, s, o);
        if (lane == 0) red[k][wid] = s;
    }
    __syncthreads();
    if (tid == 0) {
        #pragma unroll
        for (int k = 0; k < 6; k++) {
            float s = 0.f;
            #pragma unroll
            for (int w = 0; w < 8; w++) s += red[k][w];
            g_part[k][bid] = s;
        }
        __threadfence();
        unsigned prev = atomicAdd(&g_done, 1u);
        amLast = (prev == NBLK - 1);
    }
    __syncthreads();

    // ===== last block: fused finalize =====
    if (amLast) {
        __shared__ double sred[6][8];
        double acc[6] = {0, 0, 0, 0, 0, 0};
        for (int i = tid; i < NBLK; i += 256) {
            #pragma unroll
            for (int k = 0; k < 6; k++)
                acc[k] += (double)((volatile float*)g_part[k])[i];
        }
        #pragma unroll
        for (int k = 0; k < 6; k++) {
            #pragma unroll
            for (int o = 16; o > 0; o >>= 1)
                acc[k] += __shfl_down_sync(0xFFFFFFFFu, acc[k], o);
            if (lane == 0) sred[k][wid] = acc[k];
        }
        __syncthreads();
        if (tid == 0) {
            double t[6];
            #pragma unroll
            for (int k = 0; k < 6; k++) {
                double s = 0.0;
                #pragma unroll
                for (int w = 0; w < 8; w++) s += sred[k][w];
                t[k] = s;
            }
            double n2v = t[0] / fmax(t[1], 1.0);
            double wav = 1.0       * (t[2] / (3.0 * B_ * 64.0  * 64.0))
                       + (1.0/2.0) * (t[3] / (3.0 * B_ * 128.0 * 128.0))
                       + (1.0/3.0) * (t[4] / (3.0 * B_ * 256.0 * 256.0));
            double tv  = t[5] / ((double)B_ * 511.0 * 512.0);
            out[0] = (float)(1.0 * n2v + 0.2 * wav + 0.01 * tv);
            g_done = 0;   // reset for next graph replay
        }
    }
}

extern "C" void kernel_launch(void* const* d_in, const int* in_sizes, int n_in,
                              void* d_out, int out_size) {
    const float* pred  = (const float*)d_in[0];
    const float* noisy = (const float*)d_in[1];
    const void*  mask  = d_in[2];
    float* out = (float*)d_out;

    dim3 grid(W_ / TW, H_ / TH, B_);
    loss_kernel<<<grid, 256>>>(pred, noisy,
                               (const unsigned char*)mask,
                               (const unsigned int*)mask,
                               out);
}

// round 8
// speedup vs baseline: 1.1983x; 1.1983x over previous
#include <cuda_runtime.h>
#include <cuda_bf16.h>
#include <math.h>

// Loss = 1.0*n2v + 0.2*wav + 0.01*tv over pred/noisy (64,1,512,512) f32, mask bool.
// Identity: |c - soft_threshold(c, thr)| == min(|c|, thr).
// R8: cp.async pred tile (no regs), front-staged mask LDG.128s, single merged
// smem pass (TV + DWT-L1 + n2v) with row rolling. Fused last-block finalize.
// p4/n4 are pre-offset by img_off: index with IMAGE-LOCAL offsets only.

#define B_   64
#define H_   512
#define W_   512
#define TH   64
#define TW   128
#define SMS  132                       // smem row stride (floats); 132*4 % 16 == 0
#define NBLK ((W_/TW)*(H_/TH)*B_)      // 2048

#define THR1 (50.0f / 255.0f)
#define THR2 (25.0f / 255.0f)
#define THR3 (12.5f / 255.0f)

__device__ float    g_part[6][NBLK];   // [0]=n2v [1]=mask [2]=w64 [3]=w128 [4]=w256 [5]=tv
__device__ unsigned g_done;            // zero-init; last block resets each replay

#define CP_ASYNC16(dst_u32, src_ptr) \
    asm volatile("cp.async.cg.shared.global [%0], [%1], 16;" :: "r"(dst_u32), "l"(src_ptr))
#define CP_COMMIT()   asm volatile("cp.async.commit_group;")
#define CP_WAIT_ALL() asm volatile("cp.async.wait_group 0;" ::: "memory")

__device__ __forceinline__ float clipf(float x) {
    return fminf(fmaxf(x, 0.0f), 1.0f);
}

__global__ __launch_bounds__(256)
void loss_kernel(const float* __restrict__ pred,
                 const float* __restrict__ noisy,
                 const unsigned char* __restrict__ mask8,
                 const unsigned int* __restrict__ mask32,
                 float* __restrict__ out) {
    __shared__ float sm [65 * SMS];    // raw pred tile + halos (clip at read)
    __shared__ float ll1[32 * 68];
    __shared__ float ll2[16 * 36];
    __shared__ float red[6][8];
    __shared__ bool  amLast;

    const int tid  = threadIdx.x;
    const int wid  = tid >> 5;
    const int lane = tid & 31;
    const int b    = blockIdx.z;
    const int r0   = blockIdx.y * TH;
    const int c0   = blockIdx.x * TW;
    const int bid  = (blockIdx.z * gridDim.y + blockIdx.y) * gridDim.x + blockIdx.x;
    const size_t img_off = (size_t)b * H_ * W_;
    const float4* p4 = (const float4*)(pred  + img_off);
    const float4* n4 = (const float4*)(noisy + img_off);
    const bool last_row_tile = (r0 + TH == H_);
    const bool last_col_tile = (c0 + TW == W_);

    // ---- issue probe loads first (independent of everything) ----
    unsigned pw0 = mask32[tid], pw1 = mask32[tid + 256];

    // ---- cp.async: main pred tile, warp w owns rows 8w..8w+7 ----
    #pragma unroll
    for (int j = 0; j < 8; j++) {
        int r = 8 * wid + j;
        unsigned dst = (unsigned)__cvta_generic_to_shared(&sm[r * SMS + 4 * lane]);
        CP_ASYNC16(dst, p4 + (size_t)(r0 + r) * (W_ / 4) + (c0 >> 2) + lane);
    }
    // halo row 64 (next tile's first row); zero-fill at image bottom
    if (wid == 0) {
        if (!last_row_tile) {
            unsigned dst = (unsigned)__cvta_generic_to_shared(&sm[64 * SMS + 4 * lane]);
            CP_ASYNC16(dst, p4 + (size_t)(r0 + 64) * (W_ / 4) + (c0 >> 2) + lane);
        } else {
            ((float4*)&sm[64 * SMS])[lane] = make_float4(0.f, 0.f, 0.f, 0.f);
        }
    }
    CP_COMMIT();
    // halo col 128 via plain LDG (64 values; threads 64..127)
    if (tid >= 64 && tid < 128) {
        int lr = tid - 64;
        float x = 0.f;
        if (!last_col_tile)
            x = __ldg(&pred[img_off + (size_t)(r0 + lr) * W_ + c0 + TW]);
        sm[lr * SMS + TW] = x;
    }

    // ---- resolve mask layout (probe words are L2-hot across blocks) ----
    int bad = ((pw0 != 0u && pw0 != 1u && pw0 != 0x3F800000u) ||
               (pw1 != 0u && pw1 != 1u && pw1 != 0x3F800000u)) ? 1 : 0;
    const int mask_is_byte = __syncthreads_or(bad);

    // ---- front-stage all 8 mask loads (rows 8w..8w+7, cols 4*lane..) ----
    uint4    mw4[8];
    unsigned mw1[8];
    const size_t base_loff = (size_t)(r0 + 8 * wid) * W_ + c0 + 4 * lane;
    if (mask_is_byte) {
        #pragma unroll
        for (int j = 0; j < 8; j++)
            mw1[j] = __ldg((const unsigned*)(mask8 + img_off + base_loff + (size_t)j * W_));
    } else {
        #pragma unroll
        for (int j = 0; j < 8; j++)
            mw4[j] = __ldg((const uint4*)(mask32 + img_off + base_loff + (size_t)j * W_));
    }

    CP_WAIT_ALL();
    __syncthreads();

    float a_n2v = 0.f, a_msk = 0.f, a_tv = 0.f;
    float a_w1 = 0.f, a_w2 = 0.f, a_w3 = 0.f;

    // ===== single merged pass: TV + DWT-L1 + n2v, rows roll p <- d =====
    float4 p, d;
    {
        float4 raw = ((const float4*)&sm[(8 * wid) * SMS])[lane];
        p = make_float4(clipf(raw.x), clipf(raw.y), clipf(raw.z), clipf(raw.w));
    }
    const float hm = (last_col_tile && lane == 31) ? 0.f : 1.f;

    #pragma unroll
    for (int k = 0; k < 8; k++) {
        int r = 8 * wid + k;
        float4 raw = ((const float4*)&sm[(r + 1) * SMS])[lane];
        d = make_float4(clipf(raw.x), clipf(raw.y), clipf(raw.z), clipf(raw.w));
        float rt = clipf(sm[r * SMS + 4 * lane + 4]);

        // TV
        float vm = (last_row_tile && r == 63) ? 0.f : 1.f;
        a_tv += fabsf(p.y - p.x) + fabsf(p.z - p.y) + fabsf(p.w - p.z)
              + hm * fabsf(rt - p.w)
              + vm * (fabsf(d.x - p.x) + fabsf(d.y - p.y)
                    + fabsf(d.z - p.z) + fabsf(d.w - p.w));

        // DWT level 1 on even rows: pair (r, r+1) -> out row 4*wid + k/2
        if ((k & 1) == 0) {
            float s0 = p.x + p.y, t0 = d.x + d.y, u0 = p.x - p.y, v0 = d.x - d.y;
            float ch0 = (s0 - t0) * 0.5f, cv0 = (u0 + v0) * 0.5f, cd0 = (u0 - v0) * 0.5f;
            float s1 = p.z + p.w, t1 = d.z + d.w, u1 = p.z - p.w, v1 = d.z - d.w;
            float ch1 = (s1 - t1) * 0.5f, cv1 = (u1 + v1) * 0.5f, cd1 = (u1 - v1) * 0.5f;
            a_w3 += fminf(fabsf(ch0), THR3) + fminf(fabsf(cv0), THR3) + fminf(fabsf(cd0), THR3)
                  + fminf(fabsf(ch1), THR3) + fminf(fabsf(cv1), THR3) + fminf(fabsf(cd1), THR3);
            int orow = 4 * wid + (k >> 1);
            ll1[orow * 68 + 2 * lane]     = (s0 + t0) * 0.5f;
            ll1[orow * 68 + 2 * lane + 1] = (s1 + t1) * 0.5f;
        }

        // n2v from staged mask
        float m0, m1, m2, m3;
        bool any;
        if (mask_is_byte) {
            unsigned w = mw1[k];
            any = (w != 0u);
            m0 = (w & 0x000000FFu) ? 1.f : 0.f;
            m1 = (w & 0x0000FF00u) ? 1.f : 0.f;
            m2 = (w & 0x00FF0000u) ? 1.f : 0.f;
            m3 = (w & 0xFF000000u) ? 1.f : 0.f;
        } else {
            uint4 w = mw4[k];
            any = (w.x | w.y | w.z | w.w) != 0u;
            m0 = w.x ? 1.f : 0.f; m1 = w.y ? 1.f : 0.f;
            m2 = w.z ? 1.f : 0.f; m3 = w.w ? 1.f : 0.f;
        }
        a_msk += (m0 + m1) + (m2 + m3);
        if (any) {
            float4 nv = __ldg(&n4[(base_loff + (size_t)k * W_) >> 2]);
            a_n2v += fabsf(p.x - nv.x) * m0 + fabsf(p.y - nv.y) * m1
                   + fabsf(p.z - nv.z) * m2 + fabsf(p.w - nv.w) * m3;
        }

        p = d;   // roll
    }
    __syncthreads();

    // ===== Haar level 2: 32x64 -> 16x32 (THR2) =====
    {
        int i = tid >> 4, j = tid & 15;
        float4 tp = ((const float4*)&ll1[(2 * i) * 68])[j];
        float4 bo = ((const float4*)&ll1[(2 * i + 1) * 68])[j];
        float s0 = tp.x + tp.y, t0 = bo.x + bo.y, u0 = tp.x - tp.y, v0 = bo.x - bo.y;
        float ch0 = (s0 - t0) * 0.5f, cv0 = (u0 + v0) * 0.5f, cd0 = (u0 - v0) * 0.5f;
        float s1 = tp.z + tp.w, t1 = bo.z + bo.w, u1 = tp.z - tp.w, v1 = bo.z - bo.w;
        float ch1 = (s1 - t1) * 0.5f, cv1 = (u1 + v1) * 0.5f, cd1 = (u1 - v1) * 0.5f;
        a_w2 += fminf(fabsf(ch0), THR2) + fminf(fabsf(cv0), THR2) + fminf(fabsf(cd0), THR2)
              + fminf(fabsf(ch1), THR2) + fminf(fabsf(cv1), THR2) + fminf(fabsf(cd1), THR2);
        ll2[i * 36 + 2 * j]     = (s0 + t0) * 0.5f;
        ll2[i * 36 + 2 * j + 1] = (s1 + t1) * 0.5f;
    }
    __syncthreads();

    // ===== Haar level 3: 16x32 -> 8x16 details (THR1) =====
    if (tid < 64) {
        int i = tid >> 3, j = tid & 7;
        float4 tp = ((const float4*)&ll2[(2 * i) * 36])[j];
        float4 bo = ((const float4*)&ll2[(2 * i + 1) * 36])[j];
        float s0 = tp.x + tp.y, t0 = bo.x + bo.y, u0 = tp.x - tp.y, v0 = bo.x - bo.y;
        float ch0 = (s0 - t0) * 0.5f, cv0 = (u0 + v0) * 0.5f, cd0 = (u0 - v0) * 0.5f;
        float s1 = tp.z + tp.w, t1 = bo.z + bo.w, u1 = tp.z - tp.w, v1 = bo.z - bo.w;
        float ch1 = (s1 - t1) * 0.5f, cv1 = (u1 + v1) * 0.5f, cd1 = (u1 - v1) * 0.5f;
        a_w1 += fminf(fabsf(ch0), THR1) + fminf(fabsf(cv0), THR1) + fminf(fabsf(cd0), THR1)
              + fminf(fabsf(ch1), THR1) + fminf(fabsf(cv1), THR1) + fminf(fabsf(cd1), THR1);
    }

    // ===== block reduce, write partials =====
    float vals[6] = {a_n2v, a_msk, a_w1, a_w2, a_w3, a_tv};
    #pragma unroll
    for (int k = 0; k < 6; k++) {
        float s = vals[k];
        #pragma unroll
        for (int o = 16; o > 0; o >>= 1) s += __shfl_down_sync(0xFFFFFFFFu, s, o);
        if (lane == 0) red[k][wid] = s;
    }
    __syncthreads();
    if (tid == 0) {
        #pragma unroll
        for (int k = 0; k < 6; k++) {
            float s = 0.f;
            #pragma unroll
            for (int w = 0; w < 8; w++) s += red[k][w];
            g_part[k][bid] = s;
        }
        __threadfence();
        unsigned prev = atomicAdd(&g_done, 1u);
        amLast = (prev == NBLK - 1);
    }
    __syncthreads();

    // ===== last block: fused finalize =====
    if (amLast) {
        __shared__ double sred[6][8];
        double acc[6] = {0, 0, 0, 0, 0, 0};
        for (int i = tid; i < NBLK; i += 256) {
            #pragma unroll
            for (int k = 0; k < 6; k++)
                acc[k] += (double)((volatile float*)g_part[k])[i];
        }
        #pragma unroll
        for (int k = 0; k < 6; k++) {
            #pragma unroll
            for (int o = 16; o > 0; o >>= 1)
                acc[k] += __shfl_down_sync(0xFFFFFFFFu, acc[k], o);
            if (lane == 0) sred[k][wid] = acc[k];
        }
        __syncthreads();
        if (tid == 0) {
            double t[6];
            #pragma unroll
            for (int k = 0; k < 6; k++) {
                double s = 0.0;
                #pragma unroll
                for (int w = 0; w < 8; w++) s += sred[k][w];
                t[k] = s;
            }
            double n2v = t[0] / fmax(t[1], 1.0);
            double wav = 1.0       * (t[2] / (3.0 * B_ * 64.0  * 64.0))
                       + (1.0/2.0) * (t[3] / (3.0 * B_ * 128.0 * 128.0))
                       + (1.0/3.0) * (t[4] / (3.0 * B_ * 256.0 * 256.0));
            double tv  = t[5] / ((double)B_ * 511.0 * 512.0);
            out[0] = (float)(1.0 * n2v + 0.2 * wav + 0.01 * tv);
            g_done = 0;   // reset for next graph replay
        }
    }
}

extern "C" void kernel_launch(void* const* d_in, const int* in_sizes, int n_in,
                              void* d_out, int out_size) {
    const float* pred  = (const float*)d_in[0];
    const float* noisy = (const float*)d_in[1];
    const void*  mask  = d_in[2];
    float* out = (float*)d_out;

    dim3 grid(W_ / TW, H_ / TH, B_);
    loss_kernel<<<grid, 256>>>(pred, noisy,
                               (const unsigned char*)mask,
                               (const unsigned int*)mask,
                               out);
}

// round 9
// speedup vs baseline: 1.2497x; 1.0429x over previous
#include <cuda_runtime.h>
#include <cuda_bf16.h>
#include <math.h>

// Loss = 1.0*n2v + 0.2*wav + 0.01*tv over pred/noisy (64,1,512,512) f32, mask bool.
// Identity: |c - soft_threshold(c, thr)| == min(|c|, thr).
// R9: persistent 2-stage cp.async pipeline. 512 blocks x 8 tiles of 32x128;
// prefetch(t+1) overlaps compute(t) so HBM duty cycle stays high through the
// DWT/TV compute tail. DWT level-3 coeffs depend only on 8x8 pixel blocks, so
// 32-row tiles are exact. Mask layout probed per block (first 2KB, L2-hot).
// p4/n4 are pre-offset per image: index with IMAGE-LOCAL offsets only.

#define B_    64
#define H_    512
#define W_    512
#define TH    32
#define TW    128
#define SMS   132                     // smem row stride (floats); 528B % 16 == 0
#define TILES 8
#define NBLK  512                     // 4096 tiles / 8

#define THR1 (50.0f / 255.0f)
#define THR2 (25.0f / 255.0f)
#define THR3 (12.5f / 255.0f)

__device__ float    g_part[6][NBLK];  // [0]=n2v [1]=mask [2]=w64 [3]=w128 [4]=w256 [5]=tv
__device__ unsigned g_done;           // zero-init; last block resets each replay

#define CP16(dst_u32, src_ptr) \
    asm volatile("cp.async.cg.shared.global [%0], [%1], 16;" :: "r"(dst_u32), "l"(src_ptr))
#define CP4(dst_u32, src_ptr) \
    asm volatile("cp.async.ca.shared.global [%0], [%1], 4;" :: "r"(dst_u32), "l"(src_ptr))
#define CP_COMMIT() asm volatile("cp.async.commit_group;")
#define CP_WAIT1()  asm volatile("cp.async.wait_group 1;" ::: "memory")
#define CP_WAIT0()  asm volatile("cp.async.wait_group 0;" ::: "memory")

__device__ __forceinline__ float clipf(float x) { return fminf(fmaxf(x, 0.0f), 1.0f); }
__device__ __forceinline__ float4 clip4(float4 v) {
    return make_float4(clipf(v.x), clipf(v.y), clipf(v.z), clipf(v.w));
}

template <bool MB>
__device__ __forceinline__ void run_pipeline(
    const float4* __restrict__ p4, const float* __restrict__ pred_img,
    const float4* __restrict__ n4,
    const unsigned char* __restrict__ m8, const unsigned int* __restrict__ m32,
    size_t img_off, int lt_base, int wid, int lane, int tid,
    float* smbuf, float* ll1, float* ll2,
    float& a_n2v, float& a_msk, float& a_tv,
    float& a_w1, float& a_w2, float& a_w3)
{
    uint4    mc4[4], mn4[4];
    unsigned mc1[4], mn1[4];

    auto dec = [&](int k, int& r0, int& c0) {
        int lt = lt_base + k;
        r0 = (lt >> 2) * TH;
        c0 = (lt & 3) * TW;
    };
    auto prefetch = [&](float* buf, int r0, int c0) {
        #pragma unroll
        for (int j = 0; j < 4; j++) {
            int r = 4 * wid + j;
            unsigned dst = (unsigned)__cvta_generic_to_shared(&buf[r * SMS + 4 * lane]);
            CP16(dst, p4 + (size_t)(r0 + r) * (W_ / 4) + (c0 >> 2) + lane);
        }
        if (wid == 0) {                       // halo row (row 32)
            if (r0 + TH < H_) {
                unsigned dst = (unsigned)__cvta_generic_to_shared(&buf[TH * SMS + 4 * lane]);
                CP16(dst, p4 + (size_t)(r0 + TH) * (W_ / 4) + (c0 >> 2) + lane);
            } else {
                ((float4*)&buf[TH * SMS])[lane] = make_float4(0.f, 0.f, 0.f, 0.f);
            }
        }
        if (wid == 1) {                       // halo col (col 128), rows 0..31
            if (c0 + TW < W_) {
                unsigned dst = (unsigned)__cvta_generic_to_shared(&buf[lane * SMS + TW]);
                CP4(dst, pred_img + (size_t)(r0 + lane) * W_ + c0 + TW);
            } else {
                buf[lane * SMS + TW] = 0.f;
            }
        }
        CP_COMMIT();
    };
    auto ldmask = [&](int r0, int c0, uint4* w4, unsigned* w1) {
        size_t base = img_off + (size_t)(r0 + 4 * wid) * W_ + c0 + 4 * lane;
        #pragma unroll
        for (int j = 0; j < 4; j++) {
            if (MB) w1[j] = __ldg((const unsigned*)(m8 + base + (size_t)j * W_));
            else    w4[j] = __ldg((const uint4*)(m32 + base + (size_t)j * W_));
        }
    };

    int r0, c0, r0n, c0n;
    dec(0, r0, c0);
    prefetch(smbuf, r0, c0);
    ldmask(r0, c0, mc4, mc1);

    #pragma unroll 2
    for (int k = 0; k < TILES; k++) {
        if (k < TILES - 1) {
            dec(k + 1, r0n, c0n);
            prefetch(smbuf + ((k + 1) & 1) * (33 * SMS), r0n, c0n);
            ldmask(r0n, c0n, mn4, mn1);
            CP_WAIT1();
        } else {
            CP_WAIT0();
        }
        __syncthreads();

        // ---- merged pass: TV + DWT-L1 + n2v over warp-owned rows 4w..4w+3 ----
        float* buf = smbuf + (k & 1) * (33 * SMS);
        const float hm = (c0 + TW == W_ && lane == 31) ? 0.f : 1.f;
        float4 p = clip4(((const float4*)&buf[(4 * wid) * SMS])[lane]);

        #pragma unroll
        for (int j = 0; j < 4; j++) {
            int r = 4 * wid + j;
            float4 d = clip4(((const float4*)&buf[(r + 1) * SMS])[lane]);
            float rt = clipf(buf[r * SMS + 4 * lane + 4]);
            float vm = (r0 + r == H_ - 1) ? 0.f : 1.f;
            a_tv += fabsf(p.y - p.x) + fabsf(p.z - p.y) + fabsf(p.w - p.z)
                  + hm * fabsf(rt - p.w)
                  + vm * (fabsf(d.x - p.x) + fabsf(d.y - p.y)
                        + fabsf(d.z - p.z) + fabsf(d.w - p.w));

            if ((j & 1) == 0) {       // DWT L1 on pair (r, r+1) -> ll1 row 2w + j/2
                float s0 = p.x + p.y, t0 = d.x + d.y, u0 = p.x - p.y, v0 = d.x - d.y;
                float ch0 = (s0 - t0) * 0.5f, cv0 = (u0 + v0) * 0.5f, cd0 = (u0 - v0) * 0.5f;
                float s1 = p.z + p.w, t1 = d.z + d.w, u1 = p.z - p.w, v1 = d.z - d.w;
                float ch1 = (s1 - t1) * 0.5f, cv1 = (u1 + v1) * 0.5f, cd1 = (u1 - v1) * 0.5f;
                a_w3 += fminf(fabsf(ch0), THR3) + fminf(fabsf(cv0), THR3) + fminf(fabsf(cd0), THR3)
                      + fminf(fabsf(ch1), THR3) + fminf(fabsf(cv1), THR3) + fminf(fabsf(cd1), THR3);
                int orow = 2 * wid + (j >> 1);
                ll1[orow * 68 + 2 * lane]     = (s0 + t0) * 0.5f;
                ll1[orow * 68 + 2 * lane + 1] = (s1 + t1) * 0.5f;
            }

            float m0, m1, m2, m3;
            bool any;
            if (MB) {
                unsigned w = mc1[j];
                any = (w != 0u);
                m0 = (w & 0x000000FFu) ? 1.f : 0.f;
                m1 = (w & 0x0000FF00u) ? 1.f : 0.f;
                m2 = (w & 0x00FF0000u) ? 1.f : 0.f;
                m3 = (w & 0xFF000000u) ? 1.f : 0.f;
            } else {
                uint4 w = mc4[j];
                any = (w.x | w.y | w.z | w.w) != 0u;
                m0 = w.x ? 1.f : 0.f; m1 = w.y ? 1.f : 0.f;
                m2 = w.z ? 1.f : 0.f; m3 = w.w ? 1.f : 0.f;
            }
            a_msk += (m0 + m1) + (m2 + m3);
            if (any) {
                float4 nv = __ldg(&n4[((size_t)(r0 + r) * W_ + c0 + 4 * lane) >> 2]);
                a_n2v += fabsf(p.x - nv.x) * m0 + fabsf(p.y - nv.y) * m1
                       + fabsf(p.z - nv.z) * m2 + fabsf(p.w - nv.w) * m3;
            }
            p = d;
        }
        __syncthreads();

        // ---- DWT L2: 16x64 -> 8x32 (THR2) ----
        if (tid < 128) {
            int i = tid >> 4, jj = tid & 15;
            float4 tp = ((const float4*)&ll1[(2 * i) * 68])[jj];
            float4 bo = ((const float4*)&ll1[(2 * i + 1) * 68])[jj];
            float s0 = tp.x + tp.y, t0 = bo.x + bo.y, u0 = tp.x - tp.y, v0 = bo.x - bo.y;
            float ch0 = (s0 - t0) * 0.5f, cv0 = (u0 + v0) * 0.5f, cd0 = (u0 - v0) * 0.5f;
            float s1 = tp.z + tp.w, t1 = bo.z + bo.w, u1 = tp.z - tp.w, v1 = bo.z - bo.w;
            float ch1 = (s1 - t1) * 0.5f, cv1 = (u1 + v1) * 0.5f, cd1 = (u1 - v1) * 0.5f;
            a_w2 += fminf(fabsf(ch0), THR2) + fminf(fabsf(cv0), THR2) + fminf(fabsf(cd0), THR2)
                  + fminf(fabsf(ch1), THR2) + fminf(fabsf(cv1), THR2) + fminf(fabsf(cd1), THR2);
            ll2[i * 36 + 2 * jj]     = (s0 + t0) * 0.5f;
            ll2[i * 36 + 2 * jj + 1] = (s1 + t1) * 0.5f;
        }
        __syncthreads();

        // ---- DWT L3: 8x32 -> 4x16 details (THR1) ----
        if (tid < 32) {
            int i = tid >> 3, jj = tid & 7;
            float4 tp = ((const float4*)&ll2[(2 * i) * 36])[jj];
            float4 bo = ((const float4*)&ll2[(2 * i + 1) * 36])[jj];
            float s0 = tp.x + tp.y, t0 = bo.x + bo.y, u0 = tp.x - tp.y, v0 = bo.x - bo.y;
            float ch0 = (s0 - t0) * 0.5f, cv0 = (u0 + v0) * 0.5f, cd0 = (u0 - v0) * 0.5f;
            float s1 = tp.z + tp.w, t1 = bo.z + bo.w, u1 = tp.z - tp.w, v1 = bo.z - bo.w;
            float ch1 = (s1 - t1) * 0.5f, cv1 = (u1 + v1) * 0.5f, cd1 = (u1 - v1) * 0.5f;
            a_w1 += fminf(fabsf(ch0), THR1) + fminf(fabsf(cv0), THR1) + fminf(fabsf(cd0), THR1)
                  + fminf(fabsf(ch1), THR1) + fminf(fabsf(cv1), THR1) + fminf(fabsf(cd1), THR1);
        }

        r0 = r0n; c0 = c0n;
        #pragma unroll
        for (int j = 0; j < 4; j++) { mc4[j] = mn4[j]; mc1[j] = mn1[j]; }
    }
}

__global__ __launch_bounds__(256, 4)
void loss_kernel(const float* __restrict__ pred,
                 const float* __restrict__ noisy,
                 const unsigned char* __restrict__ mask8,
                 const unsigned int* __restrict__ mask32,
                 float* __restrict__ out) {
    __shared__ float smbuf[2 * 33 * SMS];   // two pipeline stages (32 rows + halo row)
    __shared__ float ll1[16 * 68];
    __shared__ float ll2[8 * 36];
    __shared__ float red[6][8];
    __shared__ bool  amLast;

    const int tid  = threadIdx.x;
    const int wid  = tid >> 5;
    const int lane = tid & 31;
    const int bk   = blockIdx.x;            // 0..511
    const int img  = bk >> 3;               // 8 blocks per image
    const int lt_base = (bk & 7) * TILES;   // local tile 0..63 within image
    const size_t img_off = (size_t)img * H_ * W_;
    const float4* p4 = (const float4*)(pred  + img_off);
    const float4* n4 = (const float4*)(noisy + img_off);
    const float*  pred_img = pred + img_off;

    // ---- mask layout probe: first 512 words (2KB, L2-hot across blocks).
    // byte-packed bools yield words outside {0,1,0x3F800000}; int32/f32 never do.
    unsigned pw0 = mask32[tid], pw1 = mask32[tid + 256];
    int bad = ((pw0 != 0u && pw0 != 1u && pw0 != 0x3F800000u) ||
               (pw1 != 0u && pw1 != 1u && pw1 != 0x3F800000u)) ? 1 : 0;
    const int mask_is_byte = __syncthreads_or(bad);

    float a_n2v = 0.f, a_msk = 0.f, a_tv = 0.f;
    float a_w1 = 0.f, a_w2 = 0.f, a_w3 = 0.f;

    if (mask_is_byte)
        run_pipeline<true >(p4, pred_img, n4, mask8, mask32, img_off, lt_base,
                            wid, lane, tid, smbuf, ll1, ll2,
                            a_n2v, a_msk, a_tv, a_w1, a_w2, a_w3);
    else
        run_pipeline<false>(p4, pred_img, n4, mask8, mask32, img_off, lt_base,
                            wid, lane, tid, smbuf, ll1, ll2,
                            a_n2v, a_msk, a_tv, a_w1, a_w2, a_w3);

    // ===== block reduce, write partials =====
    float vals[6] = {a_n2v, a_msk, a_w1, a_w2, a_w3, a_tv};
    #pragma unroll
    for (int k = 0; k < 6; k++) {
        float s = vals[k];
        #pragma unroll
        for (int o = 16; o > 0; o >>= 1) s += __shfl_down_sync(0xFFFFFFFFu, s, o);
        if (lane == 0) red[k][wid] = s;
    }
    __syncthreads();
    if (tid == 0) {
        #pragma unroll
        for (int k = 0; k < 6; k++) {
            float s = 0.f;
            #pragma unroll
            for (int w = 0; w < 8; w++) s += red[k][w];
            g_part[k][bk] = s;
        }
        __threadfence();
        unsigned prev = atomicAdd(&g_done, 1u);
        amLast = (prev == NBLK - 1);
    }
    __syncthreads();

    // ===== last block: fused finalize =====
    if (amLast) {
        __shared__ double sred[6][8];
        double acc[6] = {0, 0, 0, 0, 0, 0};
        for (int i = tid; i < NBLK; i += 256) {
            #pragma unroll
            for (int k = 0; k < 6; k++)
                acc[k] += (double)((volatile float*)g_part[k])[i];
        }
        #pragma unroll
        for (int k = 0; k < 6; k++) {
            #pragma unroll
            for (int o = 16; o > 0; o >>= 1)
                acc[k] += __shfl_down_sync(0xFFFFFFFFu, acc[k], o);
            if (lane == 0) sred[k][wid] = acc[k];
        }
        __syncthreads();
        if (tid == 0) {
            double t[6];
            #pragma unroll
            for (int k = 0; k < 6; k++) {
                double s = 0.0;
                #pragma unroll
                for (int w = 0; w < 8; w++) s += sred[k][w];
                t[k] = s;
            }
            double n2v = t[0] / fmax(t[1], 1.0);
            double wav = 1.0       * (t[2] / (3.0 * B_ * 64.0  * 64.0))
                       + (1.0/2.0) * (t[3] / (3.0 * B_ * 128.0 * 128.0))
                       + (1.0/3.0) * (t[4] / (3.0 * B_ * 256.0 * 256.0));
            double tv  = t[5] / ((double)B_ * 511.0 * 512.0);
            out[0] = (float)(1.0 * n2v + 0.2 * wav + 0.01 * tv);
            g_done = 0;   // reset for next graph replay
        }
    }
}

extern "C" void kernel_launch(void* const* d_in, const int* in_sizes, int n_in,
                              void* d_out, int out_size) {
    const float* pred  = (const float*)d_in[0];
    const float* noisy = (const float*)d_in[1];
    const void*  mask  = d_in[2];
    float* out = (float*)d_out;

    loss_kernel<<<NBLK, 256>>>(pred, noisy,
                               (const unsigned char*)mask,
                               (const unsigned int*)mask,
                               out);
}